// round 5
// baseline (speedup 1.0000x reference)
#include <cuda_runtime.h>
#include <cuda_bf16.h>
#include <cstdint>
#include <math.h>

#define NTOK    131072
#define KEXP    16
#define IN_DIM  256
#define OUT_DIM 128
#define TILE_M  128
#define MAX_TILES (NTOK / TILE_M + KEXP - 1)

#define KC      32                 // k elements per chunk
#define NCHUNK  (IN_DIM / KC)      // 8
#define AW      20                 // word stride (16 data words + 4 pad) -> conflict-free
#define NBUFB   3
#define HBLK    128                // hist/scatter blocks (256 thr x 4 tokens)

// ---------------- device scratch ----------------
__device__ int g_counts[KEXP];
__device__ int g_blockcnt[HBLK][KEXP];
__device__ int g_blockbase[HBLK][KEXP];
__device__ int g_perm[NTOK];
__device__ int g_tile_expert[MAX_TILES];
__device__ int g_tile_start[MAX_TILES];
__device__ int g_tile_len[MAX_TILES];
__device__ int g_num_tiles;
__device__ __nv_bfloat16 g_W1b[KEXP * OUT_DIM * IN_DIM];   // [e][n][k] bf16

// ---------------- helpers ----------------
__device__ __forceinline__ uint32_t smem_u32(const void* p) {
    uint32_t a;
    asm("{ .reg .u64 t; cvta.to.shared.u64 t, %1; cvt.u32.u64 %0, t; }" : "=r"(a) : "l"(p));
    return a;
}
__device__ __forceinline__ void cp_async16(uint32_t dst, const void* src) {
    asm volatile("cp.async.cg.shared.global [%0], [%1], 16;" :: "r"(dst), "l"(src) : "memory");
}
#define CP_COMMIT()  asm volatile("cp.async.commit_group;" ::: "memory")
#define CP_WAIT0()   asm volatile("cp.async.wait_group 0;" ::: "memory")
#define CP_WAIT1()   asm volatile("cp.async.wait_group 1;" ::: "memory")

__device__ __forceinline__ uint32_t pack_bf16(float lo, float hi) {
    uint32_t r;
    asm("cvt.rn.bf16x2.f32 %0, %1, %2;" : "=r"(r) : "f"(hi), "f"(lo));
    return r;
}
__device__ __forceinline__ void ldsm_x4(uint32_t& r0, uint32_t& r1, uint32_t& r2, uint32_t& r3,
                                        uint32_t addr) {
    asm volatile("ldmatrix.sync.aligned.m8n8.x4.shared.b16 {%0,%1,%2,%3}, [%4];"
                 : "=r"(r0), "=r"(r1), "=r"(r2), "=r"(r3) : "r"(addr));
}
__device__ __forceinline__ void mma_bf16(float& d0, float& d1, float& d2, float& d3,
                                         uint32_t a0, uint32_t a1, uint32_t a2, uint32_t a3,
                                         uint32_t b0, uint32_t b1) {
    asm volatile(
        "mma.sync.aligned.m16n8k16.row.col.f32.bf16.bf16.f32 "
        "{%0,%1,%2,%3}, {%4,%5,%6,%7}, {%8,%9}, {%0,%1,%2,%3};"
        : "+f"(d0), "+f"(d1), "+f"(d2), "+f"(d3)
        : "r"(a0), "r"(a1), "r"(a2), "r"(a3), "r"(b0), "r"(b1));
}

// ---------------- 1. fused: hist (blocks 0..127) + W1 transpose (blocks 128..639) ----
__global__ void fused_pre_kernel(const int* __restrict__ z, const float* __restrict__ W1) {
    int tid = threadIdx.x;
    if (blockIdx.x < HBLK) {
        // ---- histogram: per-block counts + global counts ----
        __shared__ int sh[KEXP];
        if (tid < KEXP) sh[tid] = 0;
        __syncthreads();
        int i = blockIdx.x * blockDim.x + tid;
        int4 v = ((const int4*)z)[i];
        atomicAdd(&sh[v.x], 1);
        atomicAdd(&sh[v.y], 1);
        atomicAdd(&sh[v.z], 1);
        atomicAdd(&sh[v.w], 1);
        __syncthreads();
        if (tid < KEXP) {
            g_blockcnt[blockIdx.x][tid] = sh[tid];
            atomicAdd(&g_counts[tid], sh[tid]);
        }
    } else {
        // ---- W1 transpose [e][k][n] -> [e][n][k] bf16 ----
        __shared__ float t[32][33];
        int idx = blockIdx.x - HBLK;        // 0..511
        int e  = idx >> 5;
        int bx = idx & 31;
        int k0 = (bx & 7) * 32;
        int n0 = (bx >> 3) * 32;
        int tx = tid & 31, ty = tid >> 5;   // 32 x 8
        const float* src = W1 + ((size_t)e * IN_DIM + k0) * OUT_DIM + n0;
#pragma unroll
        for (int d = 0; d < 32; d += 8)
            t[ty + d][tx] = src[(ty + d) * OUT_DIM + tx];
        __syncthreads();
        __nv_bfloat16* dst = g_W1b + ((size_t)e * OUT_DIM + n0) * IN_DIM + k0;
#pragma unroll
        for (int d = 0; d < 32; d += 8)
            dst[(ty + d) * IN_DIM + tx] = __float2bfloat16_rn(t[tx][ty + d]);
    }
}

// ---------------- 2. scan: expert offsets, tile table, per-block bases ----------------
__global__ void scan_kernel() {
    __shared__ int s_off[KEXP + 1];
    __shared__ int s_tp[KEXP + 1];
    int tid = threadIdx.x;
    if (tid == 0) {
        int off = 0, tp = 0;
        for (int e = 0; e < KEXP; e++) {
            s_off[e] = off; s_tp[e] = tp;
            int c = g_counts[e];
            off += c;
            tp += (c + TILE_M - 1) / TILE_M;
        }
        s_off[KEXP] = off; s_tp[KEXP] = tp;
        g_num_tiles = tp;
    }
    __syncthreads();
    if (tid < KEXP) {
        int base = s_off[tid];
        for (int b = 0; b < HBLK; b++) {
            g_blockbase[b][tid] = base;
            base += g_blockcnt[b][tid];
        }
    }
    int total = s_tp[KEXP];
    for (int idx = tid; idx < total; idx += blockDim.x) {
        int e = 0;
        while (s_tp[e + 1] <= idx) e++;
        int t = idx - s_tp[e];
        g_tile_expert[idx] = e;
        g_tile_start[idx] = s_off[e] + t * TILE_M;
        int rem = g_counts[e] - t * TILE_M;
        g_tile_len[idx] = rem < TILE_M ? rem : TILE_M;
    }
}

// ---------------- 3. scatter: no global atomics; resets g_counts for next replay ----
__global__ void scatter_kernel(const int* __restrict__ z) {
    __shared__ int sh_cnt[KEXP];
    __shared__ int sh_base[KEXP];
    int tid = threadIdx.x;
    if (tid < KEXP) {
        sh_cnt[tid] = 0;
        sh_base[tid] = g_blockbase[blockIdx.x][tid];
        if (blockIdx.x == 0) g_counts[tid] = 0;
    }
    __syncthreads();
    int i = blockIdx.x * blockDim.x + tid;
    int4 v = ((const int4*)z)[i];
    int r0 = atomicAdd(&sh_cnt[v.x], 1);
    int r1 = atomicAdd(&sh_cnt[v.y], 1);
    int r2 = atomicAdd(&sh_cnt[v.z], 1);
    int r3 = atomicAdd(&sh_cnt[v.w], 1);
    g_perm[sh_base[v.x] + r0] = i * 4 + 0;
    g_perm[sh_base[v.y] + r1] = i * 4 + 1;
    g_perm[sh_base[v.z] + r2] = i * 4 + 2;
    g_perm[sh_base[v.w] + r3] = i * 4 + 3;
}

// ---------------- 4. bf16 HMMA MLP with ldmatrix + 3-deep B pipeline ----------------
struct MlpSmem {
    uint32_t As[2][TILE_M][AW];         // x chunks, packed bf16x2: 20480 B
    uint32_t Bs[NBUFB][OUT_DIM][AW];    // W1b chunks:              30720 B
    int    tok[TILE_M];
    float  b1v[OUT_DIM];
    float2 w2v[OUT_DIM];
    float2 pp[TILE_M][2];
};
#define DYN_SMEM ((int)sizeof(MlpSmem))

__global__ __launch_bounds__(256, 2)
void mlp_mma_kernel(const float* __restrict__ x,
                    const float* __restrict__ b1,
                    const float* __restrict__ W2,
                    const float* __restrict__ b2,
                    float* __restrict__ out)
{
    extern __shared__ char dyn[];
    MlpSmem* s = (MlpSmem*)dyn;

    int bid = blockIdx.x;
    if (bid >= g_num_tiles) return;
    int e     = g_tile_expert[bid];
    int start = g_tile_start[bid];
    int len   = g_tile_len[bid];

    int tid = threadIdx.x;
    int wid  = tid >> 5;
    int lane = tid & 31;
    int warp_m = wid >> 1;          // 4 groups of 32 rows
    int warp_n = wid & 1;           // 2 groups of 64 cols
    int r0 = lane >> 2;             // 0..7
    int cq = lane & 3;              // 0..3

    if (tid < TILE_M) {
        s->tok[tid] = g_perm[start + (tid < len ? tid : len - 1)];
        s->b1v[tid] = b1[e * OUT_DIM + tid];
        s->w2v[tid] = ((const float2*)(W2 + (size_t)e * OUT_DIM * 2))[tid];
    }
    __syncthreads();

    const __nv_bfloat16* W1be = g_W1b + (size_t)e * OUT_DIM * IN_DIM;

    // ---- A staging: LDG fp32 -> pack bf16x2 -> STS ----
    int am = tid >> 1;
    int ah = tid & 1;
    const float4* asrc_base = (const float4*)(x + (size_t)s->tok[am] * IN_DIM + ah * 16);
    float4 pf[4];
    auto ldgA = [&](int c) {
        const float4* p = asrc_base + c * (KC / 4);
#pragma unroll
        for (int j = 0; j < 4; j++) pf[j] = p[j];
    };
    auto stsA = [&](int c) {
        uint32_t* d = &s->As[c & 1][am][ah * 8];
        uint4 w0, w1;
        w0.x = pack_bf16(pf[0].x, pf[0].y); w0.y = pack_bf16(pf[0].z, pf[0].w);
        w0.z = pack_bf16(pf[1].x, pf[1].y); w0.w = pack_bf16(pf[1].z, pf[1].w);
        w1.x = pack_bf16(pf[2].x, pf[2].y); w1.y = pack_bf16(pf[2].z, pf[2].w);
        w1.z = pack_bf16(pf[3].x, pf[3].y); w1.w = pack_bf16(pf[3].z, pf[3].w);
        *(uint4*)d       = w0;
        *(uint4*)(d + 4) = w1;
    };
    // ---- B staging via cp.async ----
    int bm = tid >> 1;
    int bq = (tid & 1) * 2;
    auto cpB = [&](int c) {
        int buf = c % NBUFB;
        const __nv_bfloat16* srcb = W1be + (size_t)bm * IN_DIM + c * KC;
        cp_async16(smem_u32(&s->Bs[buf][bm][bq * 4]),     srcb + bq * 8);
        cp_async16(smem_u32(&s->Bs[buf][bm][bq * 4 + 4]), srcb + bq * 8 + 8);
        CP_COMMIT();
    };

    // ldmatrix lane address offsets (in words)
    int q  = lane >> 3;             // matrix index 0..3
    int rr = lane & 7;
    int a_off = (warp_m * 32 + (q & 1) * 8 + rr) * AW + (q >> 1) * 4;
    int b_off = (warp_n * 64 + (q >> 1) * 8 + rr) * AW + (q & 1) * 4;
    uint32_t as0 = smem_u32(&s->As[0][0][0]);
    uint32_t bs0 = smem_u32(&s->Bs[0][0][0]);

    float acc[2][8][4];
#pragma unroll
    for (int mt = 0; mt < 2; mt++)
#pragma unroll
        for (int nt = 0; nt < 8; nt++)
#pragma unroll
            for (int v = 0; v < 4; v++) acc[mt][nt][v] = 0.f;

    ldgA(0);
    cpB(0);
    cpB(1);

#pragma unroll
    for (int i = 0; i < NCHUNK; i++) {
        stsA(i);
        if (i + 1 < NCHUNK) ldgA(i + 1);       // LDG latency covered by chunk i MMAs
        if (i < NCHUNK - 1) { CP_WAIT1(); }    // B_i ready (B_{i+1} may be in flight)
        else                { CP_WAIT0(); }
        __syncthreads();                       // A visible; chunk i-1 consumed by all
        if (i + 2 < NCHUNK) cpB(i + 2);        // refills buffer consumed at chunk i-1

        uint32_t abase = as0 + (((i & 1) * TILE_M * AW + a_off) << 2);
        uint32_t bbase = bs0 + (((i % NBUFB) * OUT_DIM * AW + b_off) << 2);
#pragma unroll
        for (int ks = 0; ks < 2; ks++) {
            uint32_t af[2][4];
#pragma unroll
            for (int mt = 0; mt < 2; mt++)
                ldsm_x4(af[mt][0], af[mt][1], af[mt][2], af[mt][3],
                        abase + ((mt * 16 * AW + ks * 8) << 2));
#pragma unroll
            for (int np = 0; np < 4; np++) {
                uint32_t b0e, b1e, b0o, b1o;
                ldsm_x4(b0e, b1e, b0o, b1o, bbase + ((np * 16 * AW + ks * 8) << 2));
#pragma unroll
                for (int mt = 0; mt < 2; mt++) {
                    mma_bf16(acc[mt][2*np][0], acc[mt][2*np][1], acc[mt][2*np][2], acc[mt][2*np][3],
                             af[mt][0], af[mt][1], af[mt][2], af[mt][3], b0e, b1e);
                    mma_bf16(acc[mt][2*np+1][0], acc[mt][2*np+1][1], acc[mt][2*np+1][2], acc[mt][2*np+1][3],
                             af[mt][0], af[mt][1], af[mt][2], af[mt][3], b0o, b1o);
                }
            }
        }
    }

    // epilogue: bias + relu + layer2 partials
    float p0[2][2], p1[2][2];
#pragma unroll
    for (int mt = 0; mt < 2; mt++)
#pragma unroll
        for (int h = 0; h < 2; h++) { p0[mt][h] = 0.f; p1[mt][h] = 0.f; }

#pragma unroll
    for (int nt = 0; nt < 8; nt++) {
        int c = warp_n * 64 + nt * 8 + cq * 2;
        float  ba = s->b1v[c], bb = s->b1v[c + 1];
        float2 wa = s->w2v[c], wb = s->w2v[c + 1];
#pragma unroll
        for (int mt = 0; mt < 2; mt++) {
            float h00 = fmaxf(acc[mt][nt][0] + ba, 0.f);
            float h01 = fmaxf(acc[mt][nt][1] + bb, 0.f);
            p0[mt][0] = fmaf(h00, wa.x, fmaf(h01, wb.x, p0[mt][0]));
            p1[mt][0] = fmaf(h00, wa.y, fmaf(h01, wb.y, p1[mt][0]));
            float h10 = fmaxf(acc[mt][nt][2] + ba, 0.f);
            float h11 = fmaxf(acc[mt][nt][3] + bb, 0.f);
            p0[mt][1] = fmaf(h10, wa.x, fmaf(h11, wb.x, p0[mt][1]));
            p1[mt][1] = fmaf(h10, wa.y, fmaf(h11, wb.y, p1[mt][1]));
        }
    }
#pragma unroll
    for (int mt = 0; mt < 2; mt++)
#pragma unroll
        for (int h = 0; h < 2; h++) {
            p0[mt][h] += __shfl_xor_sync(0xFFFFFFFFu, p0[mt][h], 1);
            p1[mt][h] += __shfl_xor_sync(0xFFFFFFFFu, p1[mt][h], 1);
            p0[mt][h] += __shfl_xor_sync(0xFFFFFFFFu, p0[mt][h], 2);
            p1[mt][h] += __shfl_xor_sync(0xFFFFFFFFu, p1[mt][h], 2);
        }
    if (cq == 0) {
#pragma unroll
        for (int mt = 0; mt < 2; mt++)
#pragma unroll
            for (int h = 0; h < 2; h++) {
                int row = warp_m * 32 + mt * 16 + h * 8 + r0;
                s->pp[row][warp_n] = make_float2(p0[mt][h], p1[mt][h]);
            }
    }
    __syncthreads();

    if (tid < TILE_M && tid < len) {
        float2 a = s->pp[tid][0], b = s->pp[tid][1];
        float l0 = a.x + b.x + b2[e * 2 + 0];
        float l1 = a.y + b.y + b2[e * 2 + 1];
        float mx = fmaxf(l0, l1);
        float e0 = expf(l0 - mx);
        float e1 = expf(l1 - mx);
        float inv = 1.f / (e0 + e1);
        ((float2*)out)[s->tok[tid]] = make_float2(e0 * inv, e1 * inv);
    }
}

// ---------------- launch ----------------
extern "C" void kernel_launch(void* const* d_in, const int* in_sizes, int n_in,
                              void* d_out, int out_size) {
    const float* x  = (const float*)d_in[0];
    const int*   z  = (const int*)d_in[1];
    const float* W1 = (const float*)d_in[2];
    const float* b1 = (const float*)d_in[3];
    const float* W2 = (const float*)d_in[4];
    const float* b2 = (const float*)d_in[5];
    float* out = (float*)d_out;

    cudaFuncSetAttribute(mlp_mma_kernel, cudaFuncAttributeMaxDynamicSharedMemorySize, DYN_SMEM);

    fused_pre_kernel<<<HBLK + 512, 256>>>(z, W1);
    scan_kernel<<<1, 256>>>();
    scatter_kernel<<<HBLK, 256>>>(z);
    mlp_mma_kernel<<<MAX_TILES, 256, DYN_SMEM>>>(x, b1, W2, b2, out);
}